// round 8
// baseline (speedup 1.0000x reference)
#include <cuda_runtime.h>
#include <cuda_bf16.h>
#include <cstdint>

// feeds: [N=65536, D=512] f32, rep: [N] int32 in [0,8), out: [S=262144, D] f32.
// out row j = feeds[i] where cumsum(rep) first exceeds j; rows >= total are 0.
//
// Pipeline:
//   1) block_sum_kernel: 64 blocks x 1024 -> g_blocksum[64]
//   2) scan_kernel:      64 blocks x 1024 -> g_cum (inclusive cumsum)
//   3) scatter_kernel:   N blocks: stage row in SMEM, then r x 2KB TMA bulk
//      stores (bypasses L1tex store wavefront path). Extra blocks zero tail.

#define MAX_N 65536
#define SCAN_BLOCKS 64
__device__ int g_cum[MAX_N];
__device__ int g_blocksum[SCAN_BLOCKS];

__global__ void block_sum_kernel(const int* __restrict__ rep) {
    __shared__ int ws[32];
    const int tid = threadIdx.x;
    const int lane = tid & 31, wid = tid >> 5;
    int x = rep[blockIdx.x * 1024 + tid];
    #pragma unroll
    for (int off = 16; off > 0; off >>= 1)
        x += __shfl_down_sync(0xffffffffu, x, off);
    if (lane == 0) ws[wid] = x;
    __syncthreads();
    if (wid == 0) {
        int w = ws[lane];
        #pragma unroll
        for (int off = 16; off > 0; off >>= 1)
            w += __shfl_down_sync(0xffffffffu, w, off);
        if (lane == 0) g_blocksum[blockIdx.x] = w;
    }
}

__global__ void scan_kernel(const int* __restrict__ rep) {
    __shared__ int ws[32];
    __shared__ int s_off;
    const int tid = threadIdx.x;
    const int lane = tid & 31, wid = tid >> 5;
    const int b = blockIdx.x;

    if (wid == 0) {
        int v = 0;
        if (lane < b) v += g_blocksum[lane];
        if (lane + 32 < b) v += g_blocksum[lane + 32];
        #pragma unroll
        for (int off = 16; off > 0; off >>= 1)
            v += __shfl_down_sync(0xffffffffu, v, off);
        if (lane == 0) s_off = v;
    }

    const int idx = b * 1024 + tid;
    int x = rep[idx];
    #pragma unroll
    for (int off = 1; off < 32; off <<= 1) {
        int y = __shfl_up_sync(0xffffffffu, x, off);
        if (lane >= off) x += y;
    }
    if (lane == 31) ws[wid] = x;
    __syncthreads();   // publishes ws AND s_off
    if (wid == 0) {
        int w = ws[lane];
        #pragma unroll
        for (int off = 1; off < 32; off <<= 1) {
            int y = __shfl_up_sync(0xffffffffu, w, off);
            if (lane >= off) w += y;
        }
        ws[lane] = w;
    }
    __syncthreads();

    g_cum[idx] = x + (wid > 0 ? ws[wid - 1] : 0) + s_off;
}

__device__ __forceinline__ uint32_t smem_addr_u32(const void* p) {
    uint32_t a;
    asm("{ .reg .u64 t; cvta.to.shared.u64 t, %1; cvt.u32.u64 %0, t; }"
        : "=r"(a) : "l"(p));
    return a;
}

// blocks [0, N): one per source row. 128 threads stage the 2KB row in SMEM,
// thread 0 issues r TMA bulk stores (2KB each) to consecutive output rows.
// blocks [N, N+TAIL_BLOCKS): grid-stride streaming-zero of [total*d4, n4).
#define TAIL_BLOCKS 2048
__global__ void scatter_kernel(const float4* __restrict__ feeds,
                               const int* __restrict__ rep,
                               float4* __restrict__ out, int d4, int N,
                               size_t n4) {
    __shared__ alignas(128) float4 row[128];
    const int b = blockIdx.x;
    if (b < N) {
        const int r = rep[b];
        if (r == 0) return;
        const int start = g_cum[b] - r;
        const int rowbytes = d4 * 16;

        row[threadIdx.x] = feeds[(size_t)b * d4 + threadIdx.x];
        __syncthreads();

        if (threadIdx.x == 0) {
            asm volatile("fence.proxy.async.shared::cta;" ::: "memory");
            const uint32_t src = smem_addr_u32(row);
            char* dst = (char*)(out + (size_t)start * d4);
            for (int k = 0; k < r; k++) {
                asm volatile(
                    "cp.async.bulk.global.shared::cta.bulk_group [%0], [%1], %2;"
                    :: "l"(dst + (size_t)k * rowbytes), "r"(src), "r"(rowbytes)
                    : "memory");
            }
            asm volatile("cp.async.bulk.commit_group;" ::: "memory");
            asm volatile("cp.async.bulk.wait_group 0;" ::: "memory");
        }
    } else {
        const int total = g_cum[N - 1];
        const size_t begin = (size_t)total * d4;
        const size_t tb = b - N;
        const size_t stride = (size_t)TAIL_BLOCKS * blockDim.x;
        const float4 z = make_float4(0.f, 0.f, 0.f, 0.f);
        for (size_t i = begin + tb * blockDim.x + threadIdx.x; i < n4;
             i += stride)
            __stcs(out + i, z);
    }
}

extern "C" void kernel_launch(void* const* d_in, const int* in_sizes, int n_in,
                              void* d_out, int out_size) {
    const float4* feeds = (const float4*)d_in[0];
    const int*    rep   = (const int*)d_in[1];
    float4*       out   = (float4*)d_out;

    const int N = in_sizes[1];                 // 65536 source rows
    const int D = in_sizes[0] / N;             // 512
    const int d4 = D / 4;                      // 128 float4 per row
    const int S = out_size / D;                // 262144 output rows
    const size_t n4 = (size_t)S * d4;

    block_sum_kernel<<<SCAN_BLOCKS, 1024>>>(rep);
    scan_kernel<<<SCAN_BLOCKS, 1024>>>(rep);
    scatter_kernel<<<N + TAIL_BLOCKS, d4>>>(feeds, rep, out, d4, N, n4);
}

// round 9
// speedup vs baseline: 1.1526x; 1.1526x over previous
#include <cuda_runtime.h>
#include <cuda_bf16.h>

// feeds: [N=65536, D=512] f32, rep: [N] int32 in [0,8), out: [S=262144, D] f32.
// out row j = feeds[i] where cumsum(rep) first exceeds j; rows >= total are 0.
//
// Pipeline (R7 scatter, trimmed scans):
//   1) block_sum_kernel: 64 blocks x 256 (int4) -> g_blocksum[64]
//   2) scan_kernel:      64 blocks x 1024 -> g_cum (inclusive cumsum)
//   3) scatter_kernel:   N blocks scatter rows (row in regs, coalesced 2KB
//      __stcs stores); extra blocks beyond N zero the tail [total, S).

#define MAX_N 65536
#define SCAN_BLOCKS 64
__device__ int g_cum[MAX_N];
__device__ int g_blocksum[SCAN_BLOCKS];

// 64 blocks x 256 threads, each thread sums one int4 (block covers 1024 ints).
__global__ void block_sum_kernel(const int4* __restrict__ rep4) {
    __shared__ int ws[8];
    const int tid = threadIdx.x;
    const int lane = tid & 31, wid = tid >> 5;
    const int4 v = __ldg(rep4 + blockIdx.x * 256 + tid);
    int x = v.x + v.y + v.z + v.w;
    #pragma unroll
    for (int off = 16; off > 0; off >>= 1)
        x += __shfl_down_sync(0xffffffffu, x, off);
    if (lane == 0) ws[wid] = x;
    __syncthreads();
    if (wid == 0 && lane < 8) {
        int w = ws[lane];
        #pragma unroll
        for (int off = 4; off > 0; off >>= 1)
            w += __shfl_down_sync(0x000000ffu, w, off);
        if (lane == 0) g_blocksum[blockIdx.x] = w;
    }
}

__global__ void scan_kernel(const int* __restrict__ rep) {
    __shared__ int ws[32];
    __shared__ int s_off;
    const int tid = threadIdx.x;
    const int lane = tid & 31, wid = tid >> 5;
    const int b = blockIdx.x;

    // Offset = sum of g_blocksum[0..b). Warp 0 fully active: predicated
    // loads, then a full-warp reduction (no divergent shfl).
    if (wid == 0) {
        int v = 0;
        if (lane < b) v += __ldg(&g_blocksum[lane]);
        if (lane + 32 < b) v += __ldg(&g_blocksum[lane + 32]);
        #pragma unroll
        for (int off = 16; off > 0; off >>= 1)
            v += __shfl_down_sync(0xffffffffu, v, off);
        if (lane == 0) s_off = v;
    }

    // Block-wide inclusive scan of 1024 items (1 per thread).
    const int idx = b * 1024 + tid;
    int x = __ldg(rep + idx);
    #pragma unroll
    for (int off = 1; off < 32; off <<= 1) {
        int y = __shfl_up_sync(0xffffffffu, x, off);
        if (lane >= off) x += y;
    }
    if (lane == 31) ws[wid] = x;
    __syncthreads();   // publishes ws AND s_off
    if (wid == 0) {
        int w = ws[lane];
        #pragma unroll
        for (int off = 1; off < 32; off <<= 1) {
            int y = __shfl_up_sync(0xffffffffu, w, off);
            if (lane >= off) w += y;
        }
        ws[lane] = w;
    }
    __syncthreads();

    g_cum[idx] = x + (wid > 0 ? ws[wid - 1] : 0) + s_off;
}

// blocks [0, N): one per source row, 128 threads x float4 = one 2KB row.
// blocks [N, N+TAIL_BLOCKS): grid-stride zero of [total*d4, n4).
// All output stores are streaming (__stcs): out is write-once, never read.
#define TAIL_BLOCKS 2048
__global__ void scatter_kernel(const float4* __restrict__ feeds,
                               const int* __restrict__ rep,
                               float4* __restrict__ out, int d4, int N,
                               size_t n4) {
    const int b = blockIdx.x;
    if (b < N) {
        const int r = rep[b];
        if (r == 0) return;
        const int start = g_cum[b] - r;
        const float4 v = feeds[(size_t)b * d4 + threadIdx.x];
        float4* dst = out + (size_t)start * d4 + threadIdx.x;
        for (int k = 0; k < r; k++)
            __stcs(dst + (size_t)k * d4, v);
    } else {
        const int total = g_cum[N - 1];
        const size_t begin = (size_t)total * d4;
        const size_t tb = b - N;
        const size_t stride = (size_t)TAIL_BLOCKS * blockDim.x;
        const float4 z = make_float4(0.f, 0.f, 0.f, 0.f);
        for (size_t i = begin + tb * blockDim.x + threadIdx.x; i < n4;
             i += stride)
            __stcs(out + i, z);
    }
}

extern "C" void kernel_launch(void* const* d_in, const int* in_sizes, int n_in,
                              void* d_out, int out_size) {
    const float4* feeds = (const float4*)d_in[0];
    const int*    rep   = (const int*)d_in[1];
    float4*       out   = (float4*)d_out;

    const int N = in_sizes[1];                 // 65536 source rows
    const int D = in_sizes[0] / N;             // 512
    const int d4 = D / 4;                      // 128 float4 per row
    const int S = out_size / D;                // 262144 output rows
    const size_t n4 = (size_t)S * d4;

    block_sum_kernel<<<SCAN_BLOCKS, 256>>>((const int4*)rep);
    scan_kernel<<<SCAN_BLOCKS, 1024>>>(rep);
    scatter_kernel<<<N + TAIL_BLOCKS, d4>>>(feeds, rep, out, d4, N, n4);
}